// round 16
// baseline (speedup 1.0000x reference)
#include <cuda_runtime.h>
#include <cuda_bf16.h>

// Problem constants: B=2097152, C=3, T=5
#define B_TOTAL       2097152
#define TPB           256
#define TILE_B        256                      // 1 b per thread per tile
#define NTILES        (B_TOTAL / TILE_B)       // 8192
#define TILES_PER_BLK 4
#define NBLK          (NTILES / TILES_PER_BLK) // 2048

#define PRED_F4       (TILE_B * 15 / 4)        // 960 float4 per tile
#define LAB_I4        (TILE_B * 5 / 4)         // 320 int4 per tile

#define FILLUP        (-100)
#define BASE_P        (0.2f / 3.0f)            // SMOOTHING / C
#define ONE_MS        0.8f                     // 1 - SMOOTHING
#define LOG2E_F       1.4426950408889634f
#define LN2_F         0.6931471805599453f

__device__ float        g_partials[NBLK];
__device__ unsigned int g_done_count = 0;

__device__ __forceinline__ void cp16(void* smem_dst, const void* gmem_src)
{
    unsigned int saddr = (unsigned int)__cvta_generic_to_shared(smem_dst);
    asm volatile("cp.async.cg.shared.global [%0], [%1], 16;\n"
                 :: "r"(saddr), "l"(gmem_src));
}
__device__ __forceinline__ void cp_commit()
{
    asm volatile("cp.async.commit_group;\n" ::: "memory");
}
template <int N>
__device__ __forceinline__ void cp_wait()
{
    asm volatile("cp.async.wait_group %0;\n" :: "n"(N) : "memory");
}
__device__ __forceinline__ float ex2f(float x)
{
    float r;
    asm("ex2.approx.ftz.f32 %0, %1;" : "=f"(r) : "f"(x));
    return r;
}
__device__ __forceinline__ float lg2f(float x)
{
    float r;
    asm("lg2.approx.ftz.f32 %0, %1;" : "=f"(r) : "f"(x));
    return r;
}

__shared__ float s_pred[2][TILE_B * 15];   // 2 x 15 KB
__shared__ int   s_lab[2][TILE_B * 5];     // 2 x 5 KB
__shared__ float s_red[TPB / 32];
__shared__ bool  s_is_last;

__device__ __forceinline__ void prefetch_tile(long tile, int buf, int tid,
                                              const float* __restrict__ pred,
                                              const int* __restrict__ lab)
{
    const float4* p4 = reinterpret_cast<const float4*>(pred + tile * (TILE_B * 15));
    float4* sp4 = reinterpret_cast<float4*>(s_pred[buf]);
#pragma unroll
    for (int k = 0; k < 4; ++k) {            // 960 chunks: 3 full + 1 partial pass
        int idx = tid + k * TPB;
        if (idx < PRED_F4) cp16(&sp4[idx], &p4[idx]);
    }
    const int4* l4 = reinterpret_cast<const int4*>(lab + tile * (TILE_B * 5));
    int4* sl4 = reinterpret_cast<int4*>(s_lab[buf]);
#pragma unroll
    for (int k = 0; k < 2; ++k) {            // 320 chunks: 1 full + 1 partial pass
        int idx = tid + k * TPB;
        if (idx < LAB_I4) cp16(&sl4[idx], &l4[idx]);
    }
}

__global__ __launch_bounds__(TPB, 5)
void ce_lsr_pipe_kernel(const float* __restrict__ pred,
                        const int* __restrict__ lab,
                        float* __restrict__ out)
{
    const int  tid   = threadIdx.x;
    const long tile0 = (long)blockIdx.x * TILES_PER_BLK;

    // Prime the pipeline
    prefetch_tile(tile0, 0, tid, pred, lab);
    cp_commit();

    float acc_lg = 0.0f, acc_d = 0.0f, acc_dl = 0.0f;

#pragma unroll
    for (int i = 0; i < TILES_PER_BLK; ++i) {
        const int buf = i & 1;
        if (i + 1 < TILES_PER_BLK) {
            prefetch_tile(tile0 + i + 1, buf ^ 1, tid, pred, lab);
            cp_commit();
            cp_wait<1>();   // tile i's group complete
        } else {
            cp_wait<0>();
        }
        __syncthreads();

        // Compute: thread handles b_local = tid. Word strides 15 / 5 are
        // coprime with 32 -> bank-conflict-free scalar LDS.
        const float* x  = s_pred[buf] + tid * 15;   // [c*5 + t]
        const int*   lb = s_lab[buf] + tid * 5;
#pragma unroll
        for (int t = 0; t < 5; ++t) {
            float x0 = x[t], x1 = x[5 + t], x2 = x[10 + t];
            int   l  = lb[t];

            // base-2 domain; x0 cancels algebraically in the final loss.
            float x0l = x0 * LOG2E_F;
            float t1  = fmaf(x1, LOG2E_F, -x0l);
            float t2  = fmaf(x2, LOG2E_F, -x0l);
            float e   = 1.0f + ex2f(t1) + ex2f(t2);   // |t| < ~9 -> safe
            float lg  = lg2f(e);

            float tl = (l == 1) ? t1 : ((l == 2) ? t2 : 0.0f);
            if (l != FILLUP) {
                acc_lg += lg;
                acc_d  += t1 + t2;
                acc_dl += tl;
            }
        }
        __syncthreads();    // buffer free before it is refilled
    }

    // Deferred scaling: loss_sum = LN2 * (acc_lg - BASE_P*acc_d - ONE_MS*acc_dl)
    float acc = LN2_F * (acc_lg - BASE_P * acc_d - ONE_MS * acc_dl);

    // ---- Deterministic block reduction ----
#pragma unroll
    for (int o = 16; o > 0; o >>= 1)
        acc += __shfl_xor_sync(0xffffffffu, acc, o);
    if ((tid & 31) == 0) s_red[tid >> 5] = acc;
    __syncthreads();

    if (tid == 0) {
        float p = 0.0f;
#pragma unroll
        for (int w = 0; w < TPB / 32; ++w) p += s_red[w];
        g_partials[blockIdx.x] = p;
        __threadfence();
        unsigned int prev = atomicAdd(&g_done_count, 1u);
        s_is_last = (prev == NBLK - 1);
    }
    __syncthreads();

    // ---- Last block: deterministic final sum + counter reset ----
    if (s_is_last) {
        __threadfence();
        float a = 0.0f;
#pragma unroll
        for (int k = 0; k < NBLK / TPB; ++k)          // 8 iters
            a += g_partials[tid + k * TPB];
#pragma unroll
        for (int o = 16; o > 0; o >>= 1)
            a += __shfl_xor_sync(0xffffffffu, a, o);
        if ((tid & 31) == 0) s_red[tid >> 5] = a;
        __syncthreads();
        if (tid == 0) {
            float total = 0.0f;
#pragma unroll
            for (int w = 0; w < TPB / 32; ++w) total += s_red[w];
            out[0] = total * (1.0f / (float)B_TOTAL);
            g_done_count = 0;   // reset for next graph replay
        }
    }
}

extern "C" void kernel_launch(void* const* d_in, const int* in_sizes, int n_in,
                              void* d_out, int out_size)
{
    const float* pred = (const float*)d_in[0];
    const int*   lab  = (const int*)d_in[1];
    float*       out  = (float*)d_out;

    ce_lsr_pipe_kernel<<<NBLK, TPB>>>(pred, lab, out);
}